// round 1
// baseline (speedup 1.0000x reference)
#include <cuda_runtime.h>
#include <cuda_bf16.h>

#define B_ 16
#define C_ 512
#define N_ 4096
#define K_ 32
#define NSPLIT 16            // K3 n-splits
#define NCHUNK (N_ / NSPLIT) // 256 n per K3 block
#define SUBT 64              // n per staged subtile
#define NP 32                // n-pairs per subtile

// Scratch (device globals — allocation-free rule)
__device__ float g_A[B_ * K_ * N_];                 // [b][k][n]   8 MB
__device__ float g_Asum[B_ * K_];
__device__ float g_part[B_ * 2 * NSPLIT * K_ * 256]; // 16 MB partials

// ---------- f32x2 packed helpers ----------
__device__ __forceinline__ unsigned long long pk2(float lo, float hi) {
    unsigned long long r;
    asm("mov.b64 %0, {%1, %2};" : "=l"(r) : "f"(lo), "f"(hi));
    return r;
}
__device__ __forceinline__ void unpk(unsigned long long v, float& lo, float& hi) {
    asm("mov.b64 {%0, %1}, %2;" : "=f"(lo), "=f"(hi) : "l"(v));
}
__device__ __forceinline__ void fma2(unsigned long long& d, unsigned long long a,
                                     unsigned long long b) {
    asm("fma.rn.f32x2 %0, %1, %2, %0;" : "+l"(d) : "l"(a), "l"(b));
}

// =====================================================================
// K1: logits + softmax.  Block = 128 threads, each thread owns 2 n.
// grid (16 n-tiles, 16 b).  dyn smem: cw_s[512][34] floats = 69632 B
// =====================================================================
__global__ void k1_softmax(const float* __restrict__ x,
                           const float* __restrict__ cw,
                           const float* __restrict__ scale) {
    extern __shared__ float cw_s[];           // [c][34] (pad keeps b64 aligned, spreads banks)
    __shared__ float sc_s[K_], c2_s[K_];
    const int tid = threadIdx.x;
    const int b   = blockIdx.y;
    const int n0  = blockIdx.x * 256 + tid * 2;

    // stage codewords transposed: cw[k][c] -> cw_s[c*34 + k]
    for (int i = tid; i < K_ * C_; i += 128) {
        int k = i >> 9, c = i & 511;
        cw_s[c * 34 + k] = cw[i];
    }
    if (tid < K_) sc_s[tid] = scale[tid];
    __syncthreads();
    if (tid < K_) {
        float s = 0.f;
        for (int c = 0; c < C_; c++) { float v = cw_s[c * 34 + tid]; s += v * v; }
        c2_s[tid] = s;
    }
    __syncthreads();

    unsigned long long acc0[16], acc1[16], x2a = 0ull;
    #pragma unroll
    for (int kk = 0; kk < 16; kk++) { acc0[kk] = 0ull; acc1[kk] = 0ull; }

    const float* xb = x + (size_t)b * C_ * N_ + n0;
    #pragma unroll 2
    for (int c = 0; c < C_; c++) {
        float2 xv = *(const float2*)(xb + (size_t)c * N_);
        unsigned long long xx0 = pk2(xv.x, xv.x);
        unsigned long long xx1 = pk2(xv.y, xv.y);
        unsigned long long xp  = pk2(xv.x, xv.y);
        fma2(x2a, xp, xp);
        const unsigned long long* cwp =
            reinterpret_cast<const unsigned long long*>(cw_s + c * 34);
        #pragma unroll
        for (int kk = 0; kk < 16; kk++) {
            unsigned long long c2 = cwp[kk];     // (cw[2kk], cw[2kk+1]) broadcast LDS.64
            fma2(acc0[kk], xx0, c2);
            fma2(acc1[kk], xx1, c2);
        }
    }

    float x2lo, x2hi;
    unpk(x2a, x2lo, x2hi);
    float l0[K_], l1[K_];
    #pragma unroll
    for (int kk = 0; kk < 16; kk++) {
        float a, bv;
        unpk(acc0[kk], a, bv);
        l0[2 * kk]     = sc_s[2 * kk]     * (x2lo - 2.f * a  + c2_s[2 * kk]);
        l0[2 * kk + 1] = sc_s[2 * kk + 1] * (x2lo - 2.f * bv + c2_s[2 * kk + 1]);
        unpk(acc1[kk], a, bv);
        l1[2 * kk]     = sc_s[2 * kk]     * (x2hi - 2.f * a  + c2_s[2 * kk]);
        l1[2 * kk + 1] = sc_s[2 * kk + 1] * (x2hi - 2.f * bv + c2_s[2 * kk + 1]);
    }
    float m0 = -1e30f, m1 = -1e30f;
    #pragma unroll
    for (int k = 0; k < K_; k++) { m0 = fmaxf(m0, l0[k]); m1 = fmaxf(m1, l1[k]); }
    float s0 = 0.f, s1 = 0.f;
    #pragma unroll
    for (int k = 0; k < K_; k++) {
        l0[k] = __expf(l0[k] - m0); s0 += l0[k];
        l1[k] = __expf(l1[k] - m1); s1 += l1[k];
    }
    float r0 = 1.f / s0, r1 = 1.f / s1;

    float2* Ap = (float2*)g_A;
    const int npr = blockIdx.x * 128 + tid;          // n-pair index
    #pragma unroll
    for (int k = 0; k < K_; k++)
        Ap[((size_t)(b * K_ + k)) * (N_ / 2) + npr] = make_float2(l0[k] * r0, l1[k] * r1);
}

// =====================================================================
// K2: Asum[b][k] = sum_n A.  grid 512, block 128.
// =====================================================================
__global__ void k2_asum() {
    __shared__ float red[4];
    const int bk  = blockIdx.x;
    const int tid = threadIdx.x;
    const float4* p = (const float4*)(g_A + (size_t)bk * N_);
    float s = 0.f;
    #pragma unroll
    for (int i = 0; i < 8; i++) {
        float4 v = p[tid + i * 128];
        s += (v.x + v.y) + (v.z + v.w);
    }
    #pragma unroll
    for (int o = 16; o; o >>= 1) s += __shfl_down_sync(0xffffffffu, s, o);
    if ((tid & 31) == 0) red[tid >> 5] = s;
    __syncthreads();
    if (tid == 0) g_Asum[bk] = (red[0] + red[1]) + (red[2] + red[3]);
}

// =====================================================================
// K3: enc partial = sum_n A[n,k]*x[n,c] over this block's n-chunk.
// grid (NSPLIT, 2 c-halves, B).  512 threads = 16 warps, warp owns 16 c.
// Lane = (kq<<2)|cq ; thread register tile: k = kq+8j (j<4), c = cw+cq+4i (i<4).
// dyn smem: A_s float2[32][33] (8448 B) + x_s float2[32][257] (65792 B) = 74240 B
// =====================================================================
__global__ void __launch_bounds__(512) k3_enc(const float* __restrict__ x) {
    extern __shared__ char smraw[];
    float2* A_s = (float2*)smraw;                 // [k][np], row stride 33
    float2* x_s = (float2*)(smraw + 8448);        // [np][c], row stride 257

    const int tid  = threadIdx.x;
    const int sidx = blockIdx.x;         // n-split
    const int ch   = blockIdx.y;         // c-half
    const int b    = blockIdx.z;
    const int lane = tid & 31, w = tid >> 5;
    const int kq = lane >> 2, cq = lane & 3;
    const int cwarp = w * 16;
    const int n0 = sidx * NCHUNK;

    unsigned long long acc[4][4];
    #pragma unroll
    for (int j = 0; j < 4; j++)
        #pragma unroll
        for (int i = 0; i < 4; i++) acc[j][i] = 0ull;

    const float* xb = x + ((size_t)b * C_ + ch * 256) * N_;

    for (int sub = 0; sub < NCHUNK / SUBT; sub++) {
        const int nbase = n0 + sub * SUBT;
        __syncthreads();
        // stage A: 32 k x 32 n-pairs
        #pragma unroll
        for (int i = tid; i < K_ * NP; i += 512) {
            int k = i >> 5, np = i & 31;
            A_s[k * 33 + np] =
                *(const float2*)(g_A + ((size_t)(b * K_ + k)) * N_ + nbase + np * 2);
        }
        // stage x: 256 c x 32 n-pairs, n-major with pad
        #pragma unroll
        for (int i = tid; i < 256 * NP; i += 512) {
            int c = i >> 5, np = i & 31;
            x_s[np * 257 + c] = *(const float2*)(xb + (size_t)c * N_ + nbase + np * 2);
        }
        __syncthreads();

        #pragma unroll 2
        for (int np = 0; np < NP; np++) {
            unsigned long long a2[4], x2v[4];
            #pragma unroll
            for (int j = 0; j < 4; j++)
                a2[j] = *reinterpret_cast<const unsigned long long*>(
                    &A_s[(kq + 8 * j) * 33 + np]);
            #pragma unroll
            for (int i = 0; i < 4; i++)
                x2v[i] = *reinterpret_cast<const unsigned long long*>(
                    &x_s[np * 257 + cwarp + cq + 4 * i]);
            #pragma unroll
            for (int j = 0; j < 4; j++)
                #pragma unroll
                for (int i = 0; i < 4; i++) fma2(acc[j][i], a2[j], x2v[i]);
        }
    }

    // write partials (deterministic, no atomics)
    float* pb = g_part + ((size_t)((b * 2 + ch) * NSPLIT + sidx)) * (K_ * 256);
    #pragma unroll
    for (int j = 0; j < 4; j++) {
        #pragma unroll
        for (int i = 0; i < 4; i++) {
            float lo, hi;
            unpk(acc[j][i], lo, hi);
            int k = kq + 8 * j;
            int c = cwarp + cq + 4 * i;
            pb[k * 256 + c] = lo + hi;
        }
    }
}

// =====================================================================
// K4: out[b,k,c] = sum_splits partial - Asum[b,k]*cw[k,c]
// =====================================================================
__global__ void k4_final(float* __restrict__ out, const float* __restrict__ cw) {
    const int i = blockIdx.x * 256 + threadIdx.x;   // 262144 total
    const int c  = i & 511;
    const int k  = (i >> 9) & 31;
    const int b  = i >> 14;
    const int ch = c >> 8, cl = c & 255;
    const float* pp = g_part + ((size_t)(b * 2 + ch)) * NSPLIT * K_ * 256;
    float s = 0.f;
    #pragma unroll
    for (int sp = 0; sp < NSPLIT; sp++) s += pp[(sp * K_ + k) * 256 + cl];
    out[i] = s - g_Asum[b * K_ + k] * cw[k * C_ + c];
}

// =====================================================================
extern "C" void kernel_launch(void* const* d_in, const int* in_sizes, int n_in,
                              void* d_out, int out_size) {
    const float* x     = (const float*)d_in[0];
    const float* cw    = (const float*)d_in[1];
    const float* scale = (const float*)d_in[2];
    float* out = (float*)d_out;

    cudaFuncSetAttribute(k1_softmax, cudaFuncAttributeMaxDynamicSharedMemorySize, 69632);
    cudaFuncSetAttribute(k3_enc,     cudaFuncAttributeMaxDynamicSharedMemorySize, 74240);

    k1_softmax<<<dim3(16, 16), 128, 69632>>>(x, cw, scale);
    k2_asum<<<B_ * K_, 128>>>();
    k3_enc<<<dim3(NSPLIT, 2, B_), 512, 74240>>>(x);
    k4_final<<<(B_ * K_ * C_) / 256, 256>>>(out, cw);
}

// round 2
// speedup vs baseline: 1.0031x; 1.0031x over previous
#include <cuda_runtime.h>
#include <cuda_bf16.h>

#define B_ 16
#define C_ 512
#define N_ 4096
#define K_ 32
#define NSPLIT 16            // K3 n-splits
#define NCHUNK (N_ / NSPLIT) // 256 n per K3 block
#define SUBT 64              // n per staged subtile
#define NP 32                // n-pairs per subtile

// Scratch (device globals — allocation-free rule)
__device__ float g_A[B_ * K_ * N_];                 // [b][k][n]   8 MB
__device__ float g_Asum[B_ * K_];
__device__ float g_part[B_ * 2 * NSPLIT * K_ * 256]; // 16 MB partials

// ---------- f32x2 packed helpers ----------
__device__ __forceinline__ unsigned long long pk2(float lo, float hi) {
    unsigned long long r;
    asm("mov.b64 %0, {%1, %2};" : "=l"(r) : "f"(lo), "f"(hi));
    return r;
}
__device__ __forceinline__ void unpk(unsigned long long v, float& lo, float& hi) {
    asm("mov.b64 {%0, %1}, %2;" : "=f"(lo), "=f"(hi) : "l"(v));
}
__device__ __forceinline__ void fma2(unsigned long long& d, unsigned long long a,
                                     unsigned long long b) {
    asm("fma.rn.f32x2 %0, %1, %2, %0;" : "+l"(d) : "l"(a), "l"(b));
}

// =====================================================================
// K1: logits + softmax.  Block = 128 threads, each thread owns 2 n.
// grid (16 n-tiles, 16 b).  dyn smem: cw_s[512][34] floats = 69632 B
// =====================================================================
__global__ void k1_softmax(const float* __restrict__ x,
                           const float* __restrict__ cw,
                           const float* __restrict__ scale) {
    extern __shared__ float cw_s[];           // [c][34] (pad keeps b64 aligned, spreads banks)
    __shared__ float sc_s[K_], c2_s[K_];
    const int tid = threadIdx.x;
    const int b   = blockIdx.y;
    const int n0  = blockIdx.x * 256 + tid * 2;

    // stage codewords transposed: cw[k][c] -> cw_s[c*34 + k]
    for (int i = tid; i < K_ * C_; i += 128) {
        int k = i >> 9, c = i & 511;
        cw_s[c * 34 + k] = cw[i];
    }
    if (tid < K_) sc_s[tid] = scale[tid];
    __syncthreads();
    if (tid < K_) {
        float s = 0.f;
        for (int c = 0; c < C_; c++) { float v = cw_s[c * 34 + tid]; s += v * v; }
        c2_s[tid] = s;
    }
    __syncthreads();

    unsigned long long acc0[16], acc1[16], x2a = 0ull;
    #pragma unroll
    for (int kk = 0; kk < 16; kk++) { acc0[kk] = 0ull; acc1[kk] = 0ull; }

    const float* xb = x + (size_t)b * C_ * N_ + n0;
    #pragma unroll 2
    for (int c = 0; c < C_; c++) {
        float2 xv = *(const float2*)(xb + (size_t)c * N_);
        unsigned long long xx0 = pk2(xv.x, xv.x);
        unsigned long long xx1 = pk2(xv.y, xv.y);
        unsigned long long xp  = pk2(xv.x, xv.y);
        fma2(x2a, xp, xp);
        const unsigned long long* cwp =
            reinterpret_cast<const unsigned long long*>(cw_s + c * 34);
        #pragma unroll
        for (int kk = 0; kk < 16; kk++) {
            unsigned long long c2 = cwp[kk];     // (cw[2kk], cw[2kk+1]) broadcast LDS.64
            fma2(acc0[kk], xx0, c2);
            fma2(acc1[kk], xx1, c2);
        }
    }

    float x2lo, x2hi;
    unpk(x2a, x2lo, x2hi);
    float l0[K_], l1[K_];
    #pragma unroll
    for (int kk = 0; kk < 16; kk++) {
        float a, bv;
        unpk(acc0[kk], a, bv);
        l0[2 * kk]     = sc_s[2 * kk]     * (x2lo - 2.f * a  + c2_s[2 * kk]);
        l0[2 * kk + 1] = sc_s[2 * kk + 1] * (x2lo - 2.f * bv + c2_s[2 * kk + 1]);
        unpk(acc1[kk], a, bv);
        l1[2 * kk]     = sc_s[2 * kk]     * (x2hi - 2.f * a  + c2_s[2 * kk]);
        l1[2 * kk + 1] = sc_s[2 * kk + 1] * (x2hi - 2.f * bv + c2_s[2 * kk + 1]);
    }
    float m0 = -1e30f, m1 = -1e30f;
    #pragma unroll
    for (int k = 0; k < K_; k++) { m0 = fmaxf(m0, l0[k]); m1 = fmaxf(m1, l1[k]); }
    float s0 = 0.f, s1 = 0.f;
    #pragma unroll
    for (int k = 0; k < K_; k++) {
        l0[k] = __expf(l0[k] - m0); s0 += l0[k];
        l1[k] = __expf(l1[k] - m1); s1 += l1[k];
    }
    float r0 = 1.f / s0, r1 = 1.f / s1;

    float2* Ap = (float2*)g_A;
    const int npr = blockIdx.x * 128 + tid;          // n-pair index
    #pragma unroll
    for (int k = 0; k < K_; k++)
        Ap[((size_t)(b * K_ + k)) * (N_ / 2) + npr] = make_float2(l0[k] * r0, l1[k] * r1);
}

// =====================================================================
// K2: Asum[b][k] = sum_n A.  grid 512, block 128.
// =====================================================================
__global__ void k2_asum() {
    __shared__ float red[4];
    const int bk  = blockIdx.x;
    const int tid = threadIdx.x;
    const float4* p = (const float4*)(g_A + (size_t)bk * N_);
    float s = 0.f;
    #pragma unroll
    for (int i = 0; i < 8; i++) {
        float4 v = p[tid + i * 128];
        s += (v.x + v.y) + (v.z + v.w);
    }
    #pragma unroll
    for (int o = 16; o; o >>= 1) s += __shfl_down_sync(0xffffffffu, s, o);
    if ((tid & 31) == 0) red[tid >> 5] = s;
    __syncthreads();
    if (tid == 0) g_Asum[bk] = (red[0] + red[1]) + (red[2] + red[3]);
}

// =====================================================================
// K3: enc partial = sum_n A[n,k]*x[n,c] over this block's n-chunk.
// grid (NSPLIT, 2 c-halves, B).  512 threads = 16 warps, warp owns 16 c.
// Lane = (kq<<2)|cq ; thread register tile: k = kq+8j (j<4), c = cw+cq+4i (i<4).
// dyn smem: A_s float2[32][33] (8448 B) + x_s float2[32][257] (65792 B) = 74240 B
// =====================================================================
__global__ void __launch_bounds__(512) k3_enc(const float* __restrict__ x) {
    extern __shared__ char smraw[];
    float2* A_s = (float2*)smraw;                 // [k][np], row stride 33
    float2* x_s = (float2*)(smraw + 8448);        // [np][c], row stride 257

    const int tid  = threadIdx.x;
    const int sidx = blockIdx.x;         // n-split
    const int ch   = blockIdx.y;         // c-half
    const int b    = blockIdx.z;
    const int lane = tid & 31, w = tid >> 5;
    const int kq = lane >> 2, cq = lane & 3;
    const int cwarp = w * 16;
    const int n0 = sidx * NCHUNK;

    unsigned long long acc[4][4];
    #pragma unroll
    for (int j = 0; j < 4; j++)
        #pragma unroll
        for (int i = 0; i < 4; i++) acc[j][i] = 0ull;

    const float* xb = x + ((size_t)b * C_ + ch * 256) * N_;

    for (int sub = 0; sub < NCHUNK / SUBT; sub++) {
        const int nbase = n0 + sub * SUBT;
        __syncthreads();
        // stage A: 32 k x 32 n-pairs
        #pragma unroll
        for (int i = tid; i < K_ * NP; i += 512) {
            int k = i >> 5, np = i & 31;
            A_s[k * 33 + np] =
                *(const float2*)(g_A + ((size_t)(b * K_ + k)) * N_ + nbase + np * 2);
        }
        // stage x: 256 c x 32 n-pairs, n-major with pad
        #pragma unroll
        for (int i = tid; i < 256 * NP; i += 512) {
            int c = i >> 5, np = i & 31;
            x_s[np * 257 + c] = *(const float2*)(xb + (size_t)c * N_ + nbase + np * 2);
        }
        __syncthreads();

        #pragma unroll 2
        for (int np = 0; np < NP; np++) {
            unsigned long long a2[4], x2v[4];
            #pragma unroll
            for (int j = 0; j < 4; j++)
                a2[j] = *reinterpret_cast<const unsigned long long*>(
                    &A_s[(kq + 8 * j) * 33 + np]);
            #pragma unroll
            for (int i = 0; i < 4; i++)
                x2v[i] = *reinterpret_cast<const unsigned long long*>(
                    &x_s[np * 257 + cwarp + cq + 4 * i]);
            #pragma unroll
            for (int j = 0; j < 4; j++)
                #pragma unroll
                for (int i = 0; i < 4; i++) fma2(acc[j][i], a2[j], x2v[i]);
        }
    }

    // write partials (deterministic, no atomics)
    float* pb = g_part + ((size_t)((b * 2 + ch) * NSPLIT + sidx)) * (K_ * 256);
    #pragma unroll
    for (int j = 0; j < 4; j++) {
        #pragma unroll
        for (int i = 0; i < 4; i++) {
            float lo, hi;
            unpk(acc[j][i], lo, hi);
            int k = kq + 8 * j;
            int c = cwarp + cq + 4 * i;
            pb[k * 256 + c] = lo + hi;
        }
    }
}

// =====================================================================
// K4: out[b,k,c] = sum_splits partial - Asum[b,k]*cw[k,c]
// =====================================================================
__global__ void k4_final(float* __restrict__ out, const float* __restrict__ cw) {
    const int i = blockIdx.x * 256 + threadIdx.x;   // 262144 total
    const int c  = i & 511;
    const int k  = (i >> 9) & 31;
    const int b  = i >> 14;
    const int ch = c >> 8, cl = c & 255;
    const float* pp = g_part + ((size_t)(b * 2 + ch)) * NSPLIT * K_ * 256;
    float s = 0.f;
    #pragma unroll
    for (int sp = 0; sp < NSPLIT; sp++) s += pp[(sp * K_ + k) * 256 + cl];
    out[i] = s - g_Asum[b * K_ + k] * cw[k * C_ + c];
}

// =====================================================================
extern "C" void kernel_launch(void* const* d_in, const int* in_sizes, int n_in,
                              void* d_out, int out_size) {
    const float* x     = (const float*)d_in[0];
    const float* cw    = (const float*)d_in[1];
    const float* scale = (const float*)d_in[2];
    float* out = (float*)d_out;

    cudaFuncSetAttribute(k1_softmax, cudaFuncAttributeMaxDynamicSharedMemorySize, 69632);
    cudaFuncSetAttribute(k3_enc,     cudaFuncAttributeMaxDynamicSharedMemorySize, 74240);

    k1_softmax<<<dim3(16, 16), 128, 69632>>>(x, cw, scale);
    k2_asum<<<B_ * K_, 128>>>();
    k3_enc<<<dim3(NSPLIT, 2, B_), 512, 74240>>>(x);
    k4_final<<<(B_ * K_ * C_) / 256, 256>>>(out, cw);
}

// round 5
// speedup vs baseline: 1.6635x; 1.6583x over previous
#include <cuda_runtime.h>
#include <cstdint>
#include <cstddef>

#define B_ 16
#define C_ 512
#define N_ 4096
#define K_ 32
#define NS_ 8                 // K3 n-splits (512 n each)
#define CT_ 4                 // K3 c-tiles (128 c each)

// Scratch (device globals — allocation-free rule)
__device__ float g_A[B_ * K_ * N_];                       // [b][k][n]  8 MB
__device__ float g_part[B_ * NS_ * CT_ * K_ * 128];       // 8 MB partials

// ---------- f32x2 packed helpers (K1) ----------
__device__ __forceinline__ unsigned long long pk2(float lo, float hi) {
    unsigned long long r;
    asm("mov.b64 %0, {%1, %2};" : "=l"(r) : "f"(lo), "f"(hi));
    return r;
}
__device__ __forceinline__ void unpk(unsigned long long v, float& lo, float& hi) {
    asm("mov.b64 {%0, %1}, %2;" : "=f"(lo), "=f"(hi) : "l"(v));
}
__device__ __forceinline__ void fma2(unsigned long long& d, unsigned long long a,
                                     unsigned long long b) {
    asm("fma.rn.f32x2 %0, %1, %2, %0;" : "+l"(d) : "l"(a), "l"(b));
}
__device__ __forceinline__ uint32_t tf32_of(float a) {
    uint32_t r;
    asm("{ .reg .b32 t; cvt.rna.tf32.f32 t, %1; mov.b32 %0, t; }" : "=r"(r) : "f"(a));
    return r;
}

// =====================================================================
// K1: logits + softmax (fp32).  Block 128 threads, 2 n each.
// grid (16, 16).  dyn smem: cw_s[512][36] floats = 73728 B.
// Deep LDG prefetch (MLP=4) + LDS.128 codeword loads.
// =====================================================================
__global__ void k1_softmax(const float* __restrict__ x,
                           const float* __restrict__ cw,
                           const float* __restrict__ scale) {
    extern __shared__ float cw_s[];           // [c][36] (16B-aligned rows)
    __shared__ float sc_s[K_], c2_s[K_];
    const int tid = threadIdx.x;
    const int b   = blockIdx.y;
    const int n0  = blockIdx.x * 256 + tid * 2;

    for (int i = tid; i < K_ * C_; i += 128) {
        int k = i >> 9, c = i & 511;
        cw_s[c * 36 + k] = cw[i];
    }
    if (tid < K_) sc_s[tid] = scale[tid];
    __syncthreads();
    if (tid < K_) {
        float s = 0.f;
        for (int c = 0; c < C_; c++) { float v = cw_s[c * 36 + tid]; s += v * v; }
        c2_s[tid] = s;
    }
    __syncthreads();

    unsigned long long acc0[16], acc1[16], x2a = 0ull;
    #pragma unroll
    for (int kk = 0; kk < 16; kk++) { acc0[kk] = 0ull; acc1[kk] = 0ull; }

    const float* xb = x + (size_t)b * C_ * N_ + n0;

    float2 pre[4];
    #pragma unroll
    for (int j = 0; j < 4; j++) pre[j] = *(const float2*)(xb + (size_t)j * N_);

    for (int c = 0; c < C_; c += 4) {
        float2 cur[4];
        #pragma unroll
        for (int j = 0; j < 4; j++) cur[j] = pre[j];
        if (c + 4 < C_) {
            #pragma unroll
            for (int j = 0; j < 4; j++)
                pre[j] = *(const float2*)(xb + (size_t)(c + 4 + j) * N_);
        }
        #pragma unroll
        for (int j = 0; j < 4; j++) {
            float2 xv = cur[j];
            unsigned long long xx0 = pk2(xv.x, xv.x);
            unsigned long long xx1 = pk2(xv.y, xv.y);
            unsigned long long xp  = pk2(xv.x, xv.y);
            fma2(x2a, xp, xp);
            const ulonglong2* cwp =
                reinterpret_cast<const ulonglong2*>(cw_s + (c + j) * 36);
            #pragma unroll
            for (int q = 0; q < 8; q++) {
                ulonglong2 cc = cwp[q];           // LDS.128 broadcast: 4 cw values
                fma2(acc0[2 * q],     xx0, cc.x);
                fma2(acc0[2 * q + 1], xx0, cc.y);
                fma2(acc1[2 * q],     xx1, cc.x);
                fma2(acc1[2 * q + 1], xx1, cc.y);
            }
        }
    }

    float x2lo, x2hi;
    unpk(x2a, x2lo, x2hi);
    float l0[K_], l1[K_];
    #pragma unroll
    for (int kk = 0; kk < 16; kk++) {
        float a, bv;
        unpk(acc0[kk], a, bv);
        l0[2 * kk]     = sc_s[2 * kk]     * (x2lo - 2.f * a  + c2_s[2 * kk]);
        l0[2 * kk + 1] = sc_s[2 * kk + 1] * (x2lo - 2.f * bv + c2_s[2 * kk + 1]);
        unpk(acc1[kk], a, bv);
        l1[2 * kk]     = sc_s[2 * kk]     * (x2hi - 2.f * a  + c2_s[2 * kk]);
        l1[2 * kk + 1] = sc_s[2 * kk + 1] * (x2hi - 2.f * bv + c2_s[2 * kk + 1]);
    }
    float m0 = -1e30f, m1 = -1e30f;
    #pragma unroll
    for (int k = 0; k < K_; k++) { m0 = fmaxf(m0, l0[k]); m1 = fmaxf(m1, l1[k]); }
    float s0 = 0.f, s1 = 0.f;
    #pragma unroll
    for (int k = 0; k < K_; k++) {
        l0[k] = __expf(l0[k] - m0); s0 += l0[k];
        l1[k] = __expf(l1[k] - m1); s1 += l1[k];
    }
    float r0 = 1.f / s0, r1 = 1.f / s1;

    float2* Ap = (float2*)g_A;
    const int npr = blockIdx.x * 128 + tid;
    #pragma unroll
    for (int k = 0; k < K_; k++)
        Ap[((size_t)(b * K_ + k)) * (N_ / 2) + npr] = make_float2(l0[k] * r0, l1[k] * r1);
}

// =====================================================================
// K3: enc partial via mma.sync tf32 (m16n8k8).
// D[32k x 128c] += sum_n A[k,n] * x[c,n]   over 512 n per CTA.
// grid (CT_=4, NS_=8, B_=16) = 512 CTAs, 256 threads (8 warps).
// Warp w owns c in [w*16, w*16+16): 2 m-tiles x 2 n-tiles of mma.
// Double-buffered smem chunks of 32 n; cvt.rna.tf32 at staging.
// =====================================================================
__device__ __forceinline__ void mma16888(float* d, const uint32_t* a, const uint32_t* b) {
    asm volatile(
        "mma.sync.aligned.m16n8k8.row.col.f32.tf32.tf32.f32 "
        "{%0,%1,%2,%3}, {%4,%5,%6,%7}, {%8,%9}, {%0,%1,%2,%3};"
        : "+f"(d[0]), "+f"(d[1]), "+f"(d[2]), "+f"(d[3])
        : "r"(a[0]), "r"(a[1]), "r"(a[2]), "r"(a[3]), "r"(b[0]), "r"(b[1]));
}

__global__ void __launch_bounds__(256) k3_enc(const float* __restrict__ x) {
    __shared__ uint32_t x_s[2][128 * 36];   // [c][n] tf32, pad 36
    __shared__ uint32_t A_s[2][32 * 36];    // [k][n] tf32, pad 36

    const int tid   = threadIdx.x;
    const int lane  = tid & 31, w = tid >> 5;
    const int ctile = blockIdx.x;
    const int ns    = blockIdx.y;
    const int b     = blockIdx.z;
    const int cwarp = w * 16;

    const float* xg = x   + ((size_t)(b * C_) + ctile * 128) * N_;
    const float* ag = g_A + ((size_t)b * K_) * N_;
    const int nb0 = ns * 512;

    float acc[2][2][4];
    #pragma unroll
    for (int mt = 0; mt < 2; mt++)
        #pragma unroll
        for (int ct = 0; ct < 2; ct++)
            #pragma unroll
            for (int j = 0; j < 4; j++) acc[mt][ct][j] = 0.f;

    // staging assignments:
    //   x: 2 threads per c-row; thread owns 16 contiguous n (4 x float4)
    //   A: 8 threads per k-row; thread owns 4 contiguous n (1 x float4)
    const int xc = tid >> 1;                 // c row 0..127
    const int xh = tid & 1;                  // n-half (16 n each)
    const int ak = tid >> 3;                 // k row 0..31
    const int aq = tid & 7;                  // n quad 0..7

    float4 xr[4], ar;
    {
        const float* xp = xg + (size_t)xc * N_ + nb0 + xh * 16;
        #pragma unroll
        for (int j = 0; j < 4; j++) xr[j] = *(const float4*)(xp + 4 * j);
        ar = *(const float4*)(ag + (size_t)ak * N_ + nb0 + aq * 4);
    }

    for (int ch = 0; ch < 16; ch++) {
        const int buf = ch & 1;
        // store staged regs (convert to tf32), STS.128
        {
            uint32_t* xd = &x_s[buf][xc * 36 + xh * 16];
            #pragma unroll
            for (int j = 0; j < 4; j++) {
                uint4 v = make_uint4(tf32_of(xr[j].x), tf32_of(xr[j].y),
                                     tf32_of(xr[j].z), tf32_of(xr[j].w));
                *(uint4*)(xd + 4 * j) = v;
            }
            uint4 av = make_uint4(tf32_of(ar.x), tf32_of(ar.y),
                                  tf32_of(ar.z), tf32_of(ar.w));
            *(uint4*)(&A_s[buf][ak * 36 + aq * 4]) = av;
        }
        __syncthreads();

        // prefetch next chunk
        if (ch < 15) {
            const int nbase = nb0 + (ch + 1) * 32;
            const float* xp = xg + (size_t)xc * N_ + nbase + xh * 16;
            #pragma unroll
            for (int j = 0; j < 4; j++) xr[j] = *(const float4*)(xp + 4 * j);
            ar = *(const float4*)(ag + (size_t)ak * N_ + nbase + aq * 4);
        }

        // compute: 4 k-steps of 8 n
        const uint32_t* As = A_s[buf];
        const uint32_t* Xs = x_s[buf];
        const int ar0 = lane >> 2;      // groupID 0..7
        const int an0 = lane & 3;       // tid-in-group 0..3
        #pragma unroll
        for (int ks = 0; ks < 4; ks++) {
            const int nk = ks * 8;
            uint32_t af[2][4], bf[2][2];
            #pragma unroll
            for (int mt = 0; mt < 2; mt++) {
                const uint32_t* ap = As + (mt * 16 + ar0) * 36 + nk + an0;
                af[mt][0] = ap[0];
                af[mt][1] = ap[8 * 36];
                af[mt][2] = ap[4];
                af[mt][3] = ap[8 * 36 + 4];
            }
            #pragma unroll
            for (int ct = 0; ct < 2; ct++) {
                const uint32_t* bp = Xs + (cwarp + ct * 8 + ar0) * 36 + nk + an0;
                bf[ct][0] = bp[0];
                bf[ct][1] = bp[4];
            }
            #pragma unroll
            for (int mt = 0; mt < 2; mt++)
                #pragma unroll
                for (int ct = 0; ct < 2; ct++)
                    mma16888(acc[mt][ct], af[mt], bf[ct]);
        }
        __syncthreads();
    }

    // epilogue -> g_part[b][ns][ctile][k][c]
    float* pb = g_part + (((size_t)(b * NS_ + ns) * CT_ + ctile) << 12);
    const int dr = lane >> 2;
    const int dc = (lane & 3) * 2;
    #pragma unroll
    for (int mt = 0; mt < 2; mt++) {
        #pragma unroll
        for (int ct = 0; ct < 2; ct++) {
            const int c0 = cwarp + ct * 8 + dc;
            const int r0 = mt * 16 + dr;
            *(float2*)(pb + r0 * 128 + c0) =
                make_float2(acc[mt][ct][0], acc[mt][ct][1]);
            *(float2*)(pb + (r0 + 8) * 128 + c0) =
                make_float2(acc[mt][ct][2], acc[mt][ct][3]);
        }
    }
}

// =====================================================================
// K4: per (b,k): Asum reduction + combine partials + subtract Asum*cw.
// grid 512 blocks, 128 threads.
// =====================================================================
__global__ void k4_final(float* __restrict__ out, const float* __restrict__ cw) {
    __shared__ float red[4];
    __shared__ float s_asum;
    const int bk  = blockIdx.x;           // b*32 + k
    const int b   = bk >> 5, k = bk & 31;
    const int tid = threadIdx.x;

    const float4* ap = (const float4*)(g_A + (size_t)bk * N_);
    float s = 0.f;
    #pragma unroll
    for (int i = 0; i < 8; i++) {
        float4 v = ap[tid + i * 128];
        s += (v.x + v.y) + (v.z + v.w);
    }
    #pragma unroll
    for (int o = 16; o; o >>= 1) s += __shfl_down_sync(0xffffffffu, s, o);
    if ((tid & 31) == 0) red[tid >> 5] = s;
    __syncthreads();
    if (tid == 0) s_asum = (red[0] + red[1]) + (red[2] + red[3]);
    __syncthreads();
    const float asum = s_asum;

    #pragma unroll
    for (int j = 0; j < 4; j++) {
        const int c  = tid + j * 128;
        const int ct = c >> 7, cl = c & 127;
        float v = 0.f;
        #pragma unroll
        for (int sp = 0; sp < NS_; sp++)
            v += g_part[(((size_t)(b * NS_ + sp) * CT_ + ct) << 12) + k * 128 + cl];
        out[(size_t)bk * C_ + c] = v - asum * cw[k * C_ + c];
    }
}

// =====================================================================
extern "C" void kernel_launch(void* const* d_in, const int* in_sizes, int n_in,
                              void* d_out, int out_size) {
    const float* x     = (const float*)d_in[0];
    const float* cw    = (const float*)d_in[1];
    const float* scale = (const float*)d_in[2];
    float* out = (float*)d_out;

    cudaFuncSetAttribute(k1_softmax, cudaFuncAttributeMaxDynamicSharedMemorySize, 73728);

    k1_softmax<<<dim3(16, 16), 128, 73728>>>(x, cw, scale);
    k3_enc<<<dim3(CT_, NS_, B_), 256>>>(x);
    k4_final<<<B_ * K_, 128>>>(out, cw);
}

// round 6
// speedup vs baseline: 2.4739x; 1.4872x over previous
#include <cuda_runtime.h>
#include <cstdint>
#include <cstddef>

#define B_ 16
#define C_ 512
#define N_ 4096
#define K_ 32
#define NS_ 8                 // K3 n-splits (512 n each)
#define CT_ 4                 // K3 c-tiles (128 c each)

// Scratch (device globals — allocation-free rule)
__device__ float g_A[B_ * K_ * N_];                       // [b][k][n]  8 MB
__device__ float g_part[B_ * NS_ * CT_ * K_ * 128];       // 8 MB partials

__device__ __forceinline__ uint32_t tf32_of(float a) {
    uint32_t r;
    asm("{ .reg .b32 t; cvt.rna.tf32.f32 t, %1; mov.b32 %0, t; }" : "=r"(r) : "f"(a));
    return r;
}
__device__ __forceinline__ void mma16888(float* d, const uint32_t* a, const uint32_t* b) {
    asm volatile(
        "mma.sync.aligned.m16n8k8.row.col.f32.tf32.tf32.f32 "
        "{%0,%1,%2,%3}, {%4,%5,%6,%7}, {%8,%9}, {%0,%1,%2,%3};"
        : "+f"(d[0]), "+f"(d[1]), "+f"(d[2]), "+f"(d[3])
        : "r"(a[0]), "r"(a[1]), "r"(a[2]), "r"(a[3]), "r"(b[0]), "r"(b[1]));
}

// =====================================================================
// K1: logits + softmax via mma.sync tf32.
// GEMM: D[128 n x 32 k] = sum_c x[n,c] * cw[k,c];  x2 kept exact fp32.
// grid (32 n-tiles, 16 b), 256 threads (8 warps, warp owns 16 n).
// dyn smem layout (bytes):
//   cw_s  [32][516] tf32   @0       66048
//   x_s 2x[32][136] tf32   @66048   34816   (reused as A_out [32][132] after)
//   sq_s  [256][4]  f32    @100864   4096
//   x2_s  [128]     f32    @104960    512
//   sc_s  [32]      f32    @105472    128
//   c2_s  [32]      f32    @105600    128   -> total 105728
// =====================================================================
#define K1_SMEM 105728

__global__ void __launch_bounds__(256) k1_softmax(const float* __restrict__ x,
                                                  const float* __restrict__ cw,
                                                  const float* __restrict__ scale) {
    extern __shared__ char sm[];
    uint32_t* cw_s = (uint32_t*)(sm);
    uint32_t* x_s  = (uint32_t*)(sm + 66048);
    float*    sq_s = (float*)(sm + 100864);
    float*    x2_s = (float*)(sm + 104960);
    float*    sc_s = (float*)(sm + 105472);
    float*    c2_s = (float*)(sm + 105600);

    const int tid  = threadIdx.x;
    const int lane = tid & 31, w = tid >> 5;
    const int b    = blockIdx.y;
    const int n0   = blockIdx.x * 128;
    const int ar0  = lane >> 2, an0 = lane & 3;

    // ---- stage cw -> cw_s[k][c] tf32 (stride 516) ----
    const float4* cwg = (const float4*)cw;
    #pragma unroll
    for (int t = 0; t < 16; t++) {
        int f = tid + t * 256;             // 0..4095
        int k = f >> 7, cq = f & 127;
        float4 v = cwg[f];
        uint4 u = make_uint4(tf32_of(v.x), tf32_of(v.y), tf32_of(v.z), tf32_of(v.w));
        *(uint4*)(cw_s + k * 516 + cq * 4) = u;
    }
    if (tid < 32) sc_s[tid] = scale[tid];
    __syncthreads();
    if (tid < 32) {                        // c2 from tf32 cw (error negligible)
        float s = 0.f;
        const uint4* row = (const uint4*)(cw_s + tid * 516);
        #pragma unroll 4
        for (int q = 0; q < 128; q++) {
            uint4 u = row[q];
            float a0 = __uint_as_float(u.x), a1 = __uint_as_float(u.y);
            float a2 = __uint_as_float(u.z), a3 = __uint_as_float(u.w);
            s += a0 * a0 + a1 * a1 + a2 * a2 + a3 * a3;
        }
        c2_s[tid] = s;
    }

    // ---- mainloop: 16 chunks of 32 c ----
    const float* xg  = x + (size_t)b * C_ * N_ + n0;
    const int cst = tid >> 5;              // c sub-row 0..7
    const int nq4 = lane * 4;              // n offset (4 n per thread)

    float sq[4] = {0.f, 0.f, 0.f, 0.f};
    float acc[4][4];
    #pragma unroll
    for (int nt = 0; nt < 4; nt++)
        #pragma unroll
        for (int j = 0; j < 4; j++) acc[nt][j] = 0.f;

    float4 xr[4];
    #pragma unroll
    for (int j = 0; j < 4; j++)
        xr[j] = *(const float4*)(xg + (size_t)(cst + 8 * j) * N_ + nq4);

    for (int ch = 0; ch < 16; ch++) {
        uint32_t* xb = x_s + (ch & 1) * (32 * 136);
        #pragma unroll
        for (int j = 0; j < 4; j++) {
            float4 v = xr[j];
            sq[0] += v.x * v.x; sq[1] += v.y * v.y;
            sq[2] += v.z * v.z; sq[3] += v.w * v.w;
            *(uint4*)(xb + (cst + 8 * j) * 136 + nq4) =
                make_uint4(tf32_of(v.x), tf32_of(v.y), tf32_of(v.z), tf32_of(v.w));
        }
        __syncthreads();
        if (ch < 15) {
            #pragma unroll
            for (int j = 0; j < 4; j++)
                xr[j] = *(const float4*)(xg +
                    (size_t)((ch + 1) * 32 + cst + 8 * j) * N_ + nq4);
        }
        // compute: 4 k-steps of 8 c
        #pragma unroll
        for (int ks = 0; ks < 4; ks++) {
            const int cb = ks * 8;
            uint32_t af[4];
            const uint32_t* ap = xb + (cb + an0) * 136 + 16 * w + ar0;
            af[0] = ap[0];
            af[1] = ap[8];
            af[2] = ap[4 * 136];
            af[3] = ap[4 * 136 + 8];
            const int gc = ch * 32 + cb + an0;
            #pragma unroll
            for (int nt = 0; nt < 4; nt++) {
                uint32_t bf[2];
                const uint32_t* bp = cw_s + (8 * nt + ar0) * 516 + gc;
                bf[0] = bp[0];
                bf[1] = bp[4];
                mma16888(acc[nt], af, bf);
            }
        }
        __syncthreads();
    }

    // ---- x2 reduce (exact fp32) ----
    *(float4*)(sq_s + tid * 4) = make_float4(sq[0], sq[1], sq[2], sq[3]);
    __syncthreads();
    if (tid < 128) {
        float s = 0.f;
        #pragma unroll
        for (int g = 0; g < 8; g++) s += sq_s[(g * 32 + (tid >> 2)) * 4 + (tid & 3)];
        x2_s[tid] = s;
    }
    __syncthreads();

    // ---- logits + softmax ----
    const float x2r0 = x2_s[16 * w + ar0];
    const float x2r1 = x2_s[16 * w + ar0 + 8];
    float lg0[8], lg1[8];
    float m0 = -1e30f, m1 = -1e30f;
    #pragma unroll
    for (int nt = 0; nt < 4; nt++) {
        #pragma unroll
        for (int j = 0; j < 2; j++) {
            const int k = 8 * nt + 2 * an0 + j;
            const float sck = sc_s[k], c2k = c2_s[k];
            float a = sck * (x2r0 - 2.f * acc[nt][j]     + c2k);
            float c = sck * (x2r1 - 2.f * acc[nt][2 + j] + c2k);
            lg0[nt * 2 + j] = a; lg1[nt * 2 + j] = c;
            m0 = fmaxf(m0, a); m1 = fmaxf(m1, c);
        }
    }
    m0 = fmaxf(m0, __shfl_xor_sync(0xffffffffu, m0, 1));
    m0 = fmaxf(m0, __shfl_xor_sync(0xffffffffu, m0, 2));
    m1 = fmaxf(m1, __shfl_xor_sync(0xffffffffu, m1, 1));
    m1 = fmaxf(m1, __shfl_xor_sync(0xffffffffu, m1, 2));
    float s0 = 0.f, s1 = 0.f;
    #pragma unroll
    for (int i = 0; i < 8; i++) {
        lg0[i] = __expf(lg0[i] - m0); s0 += lg0[i];
        lg1[i] = __expf(lg1[i] - m1); s1 += lg1[i];
    }
    s0 += __shfl_xor_sync(0xffffffffu, s0, 1);
    s0 += __shfl_xor_sync(0xffffffffu, s0, 2);
    s1 += __shfl_xor_sync(0xffffffffu, s1, 1);
    s1 += __shfl_xor_sync(0xffffffffu, s1, 2);
    const float inv0 = 1.f / s0, inv1 = 1.f / s1;

    // ---- transpose A through smem (reuse x_s region), coalesced STG ----
    float* Ao = (float*)x_s;                      // [32 k][132 n-pad]
    #pragma unroll
    for (int nt = 0; nt < 4; nt++) {
        #pragma unroll
        for (int j = 0; j < 2; j++) {
            const int k = 8 * nt + 2 * an0 + j;
            Ao[k * 132 + 16 * w + ar0]     = lg0[nt * 2 + j] * inv0;
            Ao[k * 132 + 16 * w + ar0 + 8] = lg1[nt * 2 + j] * inv1;
        }
    }
    __syncthreads();
    float* ag = g_A + (size_t)(b * K_) * N_ + n0;
    #pragma unroll
    for (int t = 0; t < 4; t++) {
        int f = tid + t * 256;                    // 0..1023
        int k = f >> 5, nq = (f & 31) * 4;
        *(float4*)(ag + (size_t)k * N_ + nq) = *(float4*)(Ao + k * 132 + nq);
    }
}

// =====================================================================
// K3: enc partial via mma.sync tf32 (m16n8k8).  (unchanged, known-good)
// D[32k x 128c] += sum_n A[k,n] * x[c,n]   over 512 n per CTA.
// =====================================================================
__global__ void __launch_bounds__(256) k3_enc(const float* __restrict__ x) {
    __shared__ uint32_t x_s[2][128 * 36];   // [c][n] tf32, pad 36
    __shared__ uint32_t A_s[2][32 * 36];    // [k][n] tf32, pad 36

    const int tid   = threadIdx.x;
    const int lane  = tid & 31, w = tid >> 5;
    const int ctile = blockIdx.x;
    const int ns    = blockIdx.y;
    const int b     = blockIdx.z;
    const int cwarp = w * 16;

    const float* xg = x   + ((size_t)(b * C_) + ctile * 128) * N_;
    const float* ag = g_A + ((size_t)b * K_) * N_;
    const int nb0 = ns * 512;

    float acc[2][2][4];
    #pragma unroll
    for (int mt = 0; mt < 2; mt++)
        #pragma unroll
        for (int ct = 0; ct < 2; ct++)
            #pragma unroll
            for (int j = 0; j < 4; j++) acc[mt][ct][j] = 0.f;

    const int xc = tid >> 1;
    const int xh = tid & 1;
    const int ak = tid >> 3;
    const int aq = tid & 7;

    float4 xr[4], ar;
    {
        const float* xp = xg + (size_t)xc * N_ + nb0 + xh * 16;
        #pragma unroll
        for (int j = 0; j < 4; j++) xr[j] = *(const float4*)(xp + 4 * j);
        ar = *(const float4*)(ag + (size_t)ak * N_ + nb0 + aq * 4);
    }

    for (int ch = 0; ch < 16; ch++) {
        const int buf = ch & 1;
        {
            uint32_t* xd = &x_s[buf][xc * 36 + xh * 16];
            #pragma unroll
            for (int j = 0; j < 4; j++) {
                uint4 v = make_uint4(tf32_of(xr[j].x), tf32_of(xr[j].y),
                                     tf32_of(xr[j].z), tf32_of(xr[j].w));
                *(uint4*)(xd + 4 * j) = v;
            }
            uint4 av = make_uint4(tf32_of(ar.x), tf32_of(ar.y),
                                  tf32_of(ar.z), tf32_of(ar.w));
            *(uint4*)(&A_s[buf][ak * 36 + aq * 4]) = av;
        }
        __syncthreads();

        if (ch < 15) {
            const int nbase = nb0 + (ch + 1) * 32;
            const float* xp = xg + (size_t)xc * N_ + nbase + xh * 16;
            #pragma unroll
            for (int j = 0; j < 4; j++) xr[j] = *(const float4*)(xp + 4 * j);
            ar = *(const float4*)(ag + (size_t)ak * N_ + nbase + aq * 4);
        }

        const uint32_t* As = A_s[buf];
        const uint32_t* Xs = x_s[buf];
        const int ar0 = lane >> 2;
        const int an0 = lane & 3;
        #pragma unroll
        for (int ks = 0; ks < 4; ks++) {
            const int nk = ks * 8;
            uint32_t af[2][4], bf[2][2];
            #pragma unroll
            for (int mt = 0; mt < 2; mt++) {
                const uint32_t* ap = As + (mt * 16 + ar0) * 36 + nk + an0;
                af[mt][0] = ap[0];
                af[mt][1] = ap[8 * 36];
                af[mt][2] = ap[4];
                af[mt][3] = ap[8 * 36 + 4];
            }
            #pragma unroll
            for (int ct = 0; ct < 2; ct++) {
                const uint32_t* bp = Xs + (cwarp + ct * 8 + ar0) * 36 + nk + an0;
                bf[ct][0] = bp[0];
                bf[ct][1] = bp[4];
            }
            #pragma unroll
            for (int mt = 0; mt < 2; mt++)
                #pragma unroll
                for (int ct = 0; ct < 2; ct++)
                    mma16888(acc[mt][ct], af[mt], bf[ct]);
        }
        __syncthreads();
    }

    float* pb = g_part + (((size_t)(b * NS_ + ns) * CT_ + ctile) << 12);
    const int dr = lane >> 2;
    const int dc = (lane & 3) * 2;
    #pragma unroll
    for (int mt = 0; mt < 2; mt++) {
        #pragma unroll
        for (int ct = 0; ct < 2; ct++) {
            const int c0 = cwarp + ct * 8 + dc;
            const int r0 = mt * 16 + dr;
            *(float2*)(pb + r0 * 128 + c0) =
                make_float2(acc[mt][ct][0], acc[mt][ct][1]);
            *(float2*)(pb + (r0 + 8) * 128 + c0) =
                make_float2(acc[mt][ct][2], acc[mt][ct][3]);
        }
    }
}

// =====================================================================
// K4: per (b,k): Asum reduction + combine partials + subtract Asum*cw.
// =====================================================================
__global__ void k4_final(float* __restrict__ out, const float* __restrict__ cw) {
    __shared__ float red[4];
    __shared__ float s_asum;
    const int bk  = blockIdx.x;
    const int b   = bk >> 5, k = bk & 31;
    const int tid = threadIdx.x;

    const float4* ap = (const float4*)(g_A + (size_t)bk * N_);
    float s = 0.f;
    #pragma unroll
    for (int i = 0; i < 8; i++) {
        float4 v = ap[tid + i * 128];
        s += (v.x + v.y) + (v.z + v.w);
    }
    #pragma unroll
    for (int o = 16; o; o >>= 1) s += __shfl_down_sync(0xffffffffu, s, o);
    if ((tid & 31) == 0) red[tid >> 5] = s;
    __syncthreads();
    if (tid == 0) s_asum = (red[0] + red[1]) + (red[2] + red[3]);
    __syncthreads();
    const float asum = s_asum;

    #pragma unroll
    for (int j = 0; j < 4; j++) {
        const int c  = tid + j * 128;
        const int ct = c >> 7, cl = c & 127;
        float v = 0.f;
        #pragma unroll
        for (int sp = 0; sp < NS_; sp++)
            v += g_part[(((size_t)(b * NS_ + sp) * CT_ + ct) << 12) + k * 128 + cl];
        out[(size_t)bk * C_ + c] = v - asum * cw[k * C_ + c];
    }
}

// =====================================================================
extern "C" void kernel_launch(void* const* d_in, const int* in_sizes, int n_in,
                              void* d_out, int out_size) {
    const float* x     = (const float*)d_in[0];
    const float* cw    = (const float*)d_in[1];
    const float* scale = (const float*)d_in[2];
    float* out = (float*)d_out;

    cudaFuncSetAttribute(k1_softmax, cudaFuncAttributeMaxDynamicSharedMemorySize, K1_SMEM);

    k1_softmax<<<dim3(32, 16), 256, K1_SMEM>>>(x, cw, scale);
    k3_enc<<<dim3(CT_, NS_, B_), 256>>>(x);
    k4_final<<<B_ * K_, 128>>>(out, cw);
}